// round 2
// baseline (speedup 1.0000x reference)
#include <cuda_runtime.h>

#define SQRTPI 1.7724538509055160273f
#define NEG_QUARTER_GAMMA (-0.14430391622538323f)   /* -0.25 * EulerGamma */

__device__ __forceinline__ float dawson_elem(float xv, const float* __restrict__ sc) {
    float ax = fabsf(xv);

    // ---------- y: Chebyshev piecewise (|x| <= 6), Clenshaw (matches reference) ----------
    float v  = -ax;
    float tb = (v + 6.0f) * (1.0f / 1.5f);  // (v - xmin)/delta, delta = 1.5
    int b = (int)ceilf(tb) - 1;
    b = b < 0 ? 0 : (b > 3 ? 3 : b);
    const float* C = sc + (b << 3);
    float c0 = C[6];
    float c1 = C[7];
    float tv = 2.0f * v;
    float n0;
    n0 = C[5] - c1; c1 = fmaf(c1, tv, c0); c0 = n0;
    n0 = C[4] - c1; c1 = fmaf(c1, tv, c0); c0 = n0;
    n0 = C[3] - c1; c1 = fmaf(c1, tv, c0); c0 = n0;
    n0 = C[2] - c1; c1 = fmaf(c1, tv, c0); c0 = n0;
    n0 = C[1] - c1; c1 = fmaf(c1, tv, c0); c0 = n0;
    n0 = C[0] - c1; c1 = fmaf(c1, tv, c0); c0 = n0;
    float y = fmaf(c1, v, c0);

    // ---------- y: asymptotic tail (|x| > 6) -- extremely rare, keep branched ----------
    if (ax > 6.0f) {
        float inv2  = 1.0f / (ax * ax);
        float inner = fmaf(inv2, -0.15625f, 0.09375f);     // 3/32 - inv2*5/32
        float mid   = fmaf(inv2, inner, -0.125f);          // -1/8 + inv2*inner
        float base  = fmaf(-0.5f, __logf(2.0f * ax), NEG_QUARTER_GAMMA);
        y = fmaf(inv2, mid, base);
    }

    // ---------- temp = pi/2 * erfi(x) for x > 0 ----------
    float temp = 0.0f;
    if (xv > 0.0f) {
        float u = xv * xv;
        if (xv <= 3.25f) {
            // pi/2*erfi(x) = x * sum_n  sqrt(pi)/(n!(2n+1)) * u^n,  n = 0..27
            float p;
            p = 2.959576e-30f;
            p = fmaf(p, u, 8.292394e-29f);
            p = fmaf(p, u, 2.240571e-27f);
            p = fmaf(p, u, 5.830061e-26f);
            p = fmaf(p, u, 1.458756e-24f);
            p = fmaf(p, u, 3.504256e-23f);
            p = fmaf(p, u, 8.067937e-22f);
            p = fmaf(p, u, 1.776914e-20f);
            p = fmaf(p, u, 3.736070e-19f);
            p = fmaf(p, u, 7.482247e-18f);
            p = fmaf(p, u, 1.423766e-16f);
            p = fmaf(p, u, 2.567377e-15f);
            p = fmaf(p, u, 4.372337e-14f);
            p = fmaf(p, u, 7.010817e-13f);
            p = fmaf(p, u, 1.054219e-11f);
            p = fmaf(p, u, 1.480123e-10f);
            p = fmaf(p, u, 1.930594e-9f);
            p = fmaf(p, u, 2.325909e-8f);
            p = fmaf(p, u, 2.570731e-7f);
            p = fmaf(p, u, 2.585871e-6f);
            p = fmaf(p, u, 2.3445156e-5f);
            p = fmaf(p, u, 1.8936474e-4f);
            p = fmaf(p, u, 1.3427681e-3f);
            p = fmaf(p, u, 8.2058049e-3f);
            p = fmaf(p, u, 4.2201282e-2f);
            p = fmaf(p, u, 1.7724539e-1f);
            p = fmaf(p, u, 5.9081795e-1f);
            p = fmaf(p, u, 1.7724539f);
            temp = xv * p;
        } else {
            // pi/2*erfi(x) = (sqrt(pi)/2) * e^{x^2}/x * sum_k (2k-1)!! w^k, w = 1/(2x^2), k=0..10
            float w = 0.5f / u;
            float P;
            P = 6.54729075e8f;             // (19)!!
            P = fmaf(P, w, 3.4459425e7f);  // (17)!!
            P = fmaf(P, w, 2027025.0f);    // (15)!!
            P = fmaf(P, w, 135135.0f);     // (13)!!
            P = fmaf(P, w, 10395.0f);      // (11)!!
            P = fmaf(P, w, 945.0f);
            P = fmaf(P, w, 105.0f);
            P = fmaf(P, w, 15.0f);
            P = fmaf(P, w, 3.0f);
            P = fmaf(P, w, 1.0f);
            P = fmaf(P, w, 1.0f);
            temp = (0.5f * SQRTPI) * expf(u) * P / xv;
        }
    }
    return y + temp;
}

__global__ __launch_bounds__(256)
void DawsonIntegrate_22505628631234_kernel(const float* __restrict__ x,
                                           const float* __restrict__ cheb,
                                           float* __restrict__ out,
                                           int n, int n4) {
    __shared__ float sc[32];
    if (threadIdx.x < 32) sc[threadIdx.x] = cheb[threadIdx.x];
    __syncthreads();

    int i = blockIdx.x * blockDim.x + threadIdx.x;
    if (i < n4) {
        float4 vin = reinterpret_cast<const float4*>(x)[i];
        float4 r;
        r.x = dawson_elem(vin.x, sc);
        r.y = dawson_elem(vin.y, sc);
        r.z = dawson_elem(vin.z, sc);
        r.w = dawson_elem(vin.w, sc);
        reinterpret_cast<float4*>(out)[i] = r;
    } else if (i == n4) {
        // scalar tail (n % 4 elements), handled by one thread
        for (int j = n4 << 2; j < n; ++j)
            out[j] = dawson_elem(x[j], sc);
    }
}

extern "C" void kernel_launch(void* const* d_in, const int* in_sizes, int n_in,
                              void* d_out, int out_size) {
    const float* x    = (const float*)d_in[0];
    const float* cheb = (const float*)d_in[1];
    float* out        = (float*)d_out;
    int n  = in_sizes[0];
    int n4 = n >> 2;
    int total = n4 + ((n & 3) ? 1 : 0);
    int threads = 256;
    int blocks = (total + threads - 1) / threads;
    if (blocks == 0) blocks = 1;
    DawsonIntegrate_22505628631234_kernel<<<blocks, threads>>>(x, cheb, out, n, n4);
}

// round 4
// speedup vs baseline: 1.0037x; 1.0037x over previous
#include <cuda_runtime.h>

#define SQRTPI 1.7724538509055160273f
#define NEG_QUARTER_GAMMA (-0.14430391622538323f)   /* -0.25 * EulerGamma */

__device__ __forceinline__ float dawson_elem(float xv, const float* __restrict__ sc) {
    float ax = fabsf(xv);

    // ---------- y: Chebyshev piecewise (|x| <= 6), Clenshaw (matches reference) ----------
    float v  = -ax;
    float tb = (v + 6.0f) * (1.0f / 1.5f);  // (v - xmin)/delta, delta = 1.5
    int b = (int)ceilf(tb) - 1;
    b = b < 0 ? 0 : (b > 3 ? 3 : b);
    const float* C = sc + (b << 3);
    float c0 = C[6];
    float c1 = C[7];
    float tv = 2.0f * v;
    float n0;
    n0 = C[5] - c1; c1 = fmaf(c1, tv, c0); c0 = n0;
    n0 = C[4] - c1; c1 = fmaf(c1, tv, c0); c0 = n0;
    n0 = C[3] - c1; c1 = fmaf(c1, tv, c0); c0 = n0;
    n0 = C[2] - c1; c1 = fmaf(c1, tv, c0); c0 = n0;
    n0 = C[1] - c1; c1 = fmaf(c1, tv, c0); c0 = n0;
    n0 = C[0] - c1; c1 = fmaf(c1, tv, c0); c0 = n0;
    float y = fmaf(c1, v, c0);

    // ---------- y: asymptotic tail (|x| > 6) -- extremely rare, keep branched ----------
    if (ax > 6.0f) {
        float inv2  = 1.0f / (ax * ax);
        float inner = fmaf(inv2, -0.15625f, 0.09375f);     // 3/32 - inv2*5/32
        float mid   = fmaf(inv2, inner, -0.125f);          // -1/8 + inv2*inner
        float base  = fmaf(-0.5f, __logf(2.0f * ax), NEG_QUARTER_GAMMA);
        y = fmaf(inv2, mid, base);
    }

    // ---------- temp = pi/2 * erfi(x) for x > 0 ----------
    float temp = 0.0f;
    if (xv > 0.0f) {
        float u = xv * xv;
        if (xv <= 3.25f) {
            // pi/2*erfi(x) = x * sum_n  sqrt(pi)/(n!(2n+1)) * u^n,  n = 0..27
            float p;
            p = 2.959576e-30f;
            p = fmaf(p, u, 8.292394e-29f);
            p = fmaf(p, u, 2.240571e-27f);
            p = fmaf(p, u, 5.830061e-26f);
            p = fmaf(p, u, 1.458756e-24f);
            p = fmaf(p, u, 3.504256e-23f);
            p = fmaf(p, u, 8.067937e-22f);
            p = fmaf(p, u, 1.776914e-20f);
            p = fmaf(p, u, 3.736070e-19f);
            p = fmaf(p, u, 7.482247e-18f);
            p = fmaf(p, u, 1.423766e-16f);
            p = fmaf(p, u, 2.567377e-15f);
            p = fmaf(p, u, 4.372337e-14f);
            p = fmaf(p, u, 7.010817e-13f);
            p = fmaf(p, u, 1.054219e-11f);
            p = fmaf(p, u, 1.480123e-10f);
            p = fmaf(p, u, 1.930594e-9f);
            p = fmaf(p, u, 2.325909e-8f);
            p = fmaf(p, u, 2.570731e-7f);
            p = fmaf(p, u, 2.585871e-6f);
            p = fmaf(p, u, 2.3445156e-5f);
            p = fmaf(p, u, 1.8936474e-4f);
            p = fmaf(p, u, 1.3427681e-3f);
            p = fmaf(p, u, 8.2058049e-3f);
            p = fmaf(p, u, 4.2201282e-2f);
            p = fmaf(p, u, 1.7724539e-1f);
            p = fmaf(p, u, 5.9081795e-1f);
            p = fmaf(p, u, 1.7724539f);
            temp = xv * p;
        } else {
            // pi/2*erfi(x) = (sqrt(pi)/2) * e^{x^2}/x * sum_k (2k-1)!! w^k, w = 1/(2x^2), k=0..10
            float w = 0.5f / u;
            float P;
            P = 6.54729075e8f;             // (19)!!
            P = fmaf(P, w, 3.4459425e7f);  // (17)!!
            P = fmaf(P, w, 2027025.0f);    // (15)!!
            P = fmaf(P, w, 135135.0f);     // (13)!!
            P = fmaf(P, w, 10395.0f);      // (11)!!
            P = fmaf(P, w, 945.0f);
            P = fmaf(P, w, 105.0f);
            P = fmaf(P, w, 15.0f);
            P = fmaf(P, w, 3.0f);
            P = fmaf(P, w, 1.0f);
            P = fmaf(P, w, 1.0f);
            temp = (0.5f * SQRTPI) * expf(u) * P / xv;
        }
    }
    return y + temp;
}

__global__ __launch_bounds__(256)
void DawsonIntegrate_22505628631234_kernel(const float* __restrict__ x,
                                           const float* __restrict__ cheb,
                                           float* __restrict__ out,
                                           int n, int n4) {
    __shared__ float sc[32];
    if (threadIdx.x < 32) sc[threadIdx.x] = cheb[threadIdx.x];
    __syncthreads();

    int i = blockIdx.x * blockDim.x + threadIdx.x;
    if (i < n4) {
        float4 vin = reinterpret_cast<const float4*>(x)[i];
        float4 r;
        r.x = dawson_elem(vin.x, sc);
        r.y = dawson_elem(vin.y, sc);
        r.z = dawson_elem(vin.z, sc);
        r.w = dawson_elem(vin.w, sc);
        reinterpret_cast<float4*>(out)[i] = r;
    } else if (i == n4) {
        // scalar tail (n % 4 elements), handled by one thread
        for (int j = n4 << 2; j < n; ++j)
            out[j] = dawson_elem(x[j], sc);
    }
}

extern "C" void kernel_launch(void* const* d_in, const int* in_sizes, int n_in,
                              void* d_out, int out_size) {
    const float* x    = (const float*)d_in[0];
    const float* cheb = (const float*)d_in[1];
    float* out        = (float*)d_out;
    int n  = in_sizes[0];
    int n4 = n >> 2;
    int total = n4 + ((n & 3) ? 1 : 0);
    int threads = 256;
    int blocks = (total + threads - 1) / threads;
    if (blocks == 0) blocks = 1;
    DawsonIntegrate_22505628631234_kernel<<<blocks, threads>>>(x, cheb, out, n, n4);
}